// round 9
// baseline (speedup 1.0000x reference)
#include <cuda_runtime.h>
#include <cuda_bf16.h>
#include <cstdint>

// ---------------- problem constants ----------------
#define BATCH   16384
#define INDIM   219
#define HID     64
#define NCH     14          // K chunks
#define CK      144         // K per chunk = 16 bases + 16*8 splines
#define KTOT    2016
#define MROWS   64
#define THREADS 256
#define AS      152         // A smem row stride (elems) -> 304 B
#define WS      72          // W smem row stride (elems) -> 144 B
#define WCHUNK_HALF 20736   // 144 k * 144 B
#define WCHUNK      41472

// Pre-split, pre-padded W chunk images: [chunk][hi 20736 | lo 20736]
__device__ __align__(16) unsigned char Wimg[NCH * WCHUNK];

// ---------------- smem layout ----------------
#define SM_SIDX 0
#define SM_A    256                       // Ah: 64*304 = 19456
#define SM_AL   (SM_A + MROWS * AS * 2)   // Al: 19456
#define SM_W    (SM_AL + MROWS * AS * 2)  // 41472
#define SMEM_TOTAL (SM_W + WCHUNK)

// ---------------- PTX helpers ----------------
__device__ __forceinline__ uint32_t smem_u32(const void* p) {
    uint32_t a;
    asm("{ .reg .u64 t; cvta.to.shared.u64 t, %1; cvt.u32.u64 %0, t; }"
        : "=r"(a) : "l"(p));
    return a;
}
__device__ __forceinline__ void ldsm4(uint32_t* d, uint32_t addr) {
    asm volatile("ldmatrix.sync.aligned.m8n8.x4.shared.b16 {%0,%1,%2,%3}, [%4];"
                 : "=r"(d[0]), "=r"(d[1]), "=r"(d[2]), "=r"(d[3]) : "r"(addr));
}
__device__ __forceinline__ void ldsm4t(uint32_t* d, uint32_t addr) {
    asm volatile("ldmatrix.sync.aligned.m8n8.x4.trans.shared.b16 {%0,%1,%2,%3}, [%4];"
                 : "=r"(d[0]), "=r"(d[1]), "=r"(d[2]), "=r"(d[3]) : "r"(addr));
}
__device__ __forceinline__ void mma16816(float* c, const uint32_t* a,
                                         uint32_t b0, uint32_t b1) {
    asm volatile("mma.sync.aligned.m16n8k16.row.col.f32.bf16.bf16.f32 "
                 "{%0,%1,%2,%3}, {%4,%5,%6,%7}, {%8,%9}, {%0,%1,%2,%3};"
                 : "+f"(c[0]), "+f"(c[1]), "+f"(c[2]), "+f"(c[3])
                 : "r"(a[0]), "r"(a[1]), "r"(a[2]), "r"(a[3]), "r"(b0), "r"(b1));
}
__device__ __forceinline__ void cp16(uint32_t dst, const void* src) {
    asm volatile("cp.async.cg.shared.global [%0], [%1], 16;" :: "r"(dst), "l"(src));
}

// ---------------- math helpers ----------------
__device__ __forceinline__ float siluf(float x) { return x / (1.0f + __expf(-x)); }

// Exact closed form of the reference Cox-de Boor cubic recursion on the
// uniform extended grid (knots -2.2 + 0.4*j).
__device__ __forceinline__ void spline_local(float x, int& m, float& n0, float& n1,
                                             float& n2, float& n3) {
    float tt = (x + 2.2f) * 2.5f;
    float mf = floorf(tt);
    m = (int)mf;
    float u = tt - mf, v = 1.0f - u;
    float u2 = u * u, u3 = u2 * u;
    n0 = v * v * v * (1.0f / 6.0f);
    n1 = (3.0f * u3 - 6.0f * u2 + 4.0f) * (1.0f / 6.0f);
    n2 = (-3.0f * u3 + 3.0f * u2 + 3.0f * u + 1.0f) * (1.0f / 6.0f);
    n3 = u3 * (1.0f / 6.0f);
}
// v[0] = silu, v[1..8] = spline basis values
__device__ __forceinline__ void fill_slots(float x, float* v) {
    v[0] = siluf(x);
    int m; float n0, n1, n2, n3;
    spline_local(x, m, n0, n1, n2, n3);
    if (m >= 0 && m <= 10) {
        int j0 = m - 3;
        if (m >= 3)           v[1 + j0]     = n0;
        if (m >= 2 && m <= 9) v[1 + j0 + 1] = n1;
        if (m >= 1 && m <= 8) v[1 + j0 + 2] = n2;
        if (m <= 7)           v[1 + m]      = n3;
    }
}
__device__ __forceinline__ void cvt_pair(float v0, float v1, uint32_t& hi, uint32_t& lo) {
    __nv_bfloat16 h0 = __float2bfloat16_rn(v0), h1 = __float2bfloat16_rn(v1);
    float r0 = v0 - __bfloat162float(h0), r1 = v1 - __bfloat162float(h1);
    __nv_bfloat16 l0 = __float2bfloat16_rn(r0), l1 = __float2bfloat16_rn(r1);
    hi = ((uint32_t)__bfloat16_as_ushort(h1) << 16) | __bfloat16_as_ushort(h0);
    lo = ((uint32_t)__bfloat16_as_ushort(l1) << 16) | __bfloat16_as_ushort(l0);
}
__device__ __forceinline__ float fetch_x(int i, int rb,
                                         const float* __restrict__ hist,
                                         const float* __restrict__ statf,
                                         const float* __restrict__ timef,
                                         const float* __restrict__ emb, int sid) {
    if (i < 192) return hist[rb * 192 + i];
    if (i < 195) return statf[rb * 3 + (i - 192)];
    if (i < 203) return timef[rb * 8 + (i - 195)];
    return emb[sid * 16 + (i - 203)];
}

// ---------------- W repack: split hi/lo, chunked, padded rows ----------------
__global__ void repack_kernel(const float* __restrict__ wb1, const float* __restrict__ c1) {
    int idx = blockIdx.x * blockDim.x + threadIdx.x;
    if (idx >= KTOT * WS) return;
    int k = idx / WS, n = idx - (idx / WS) * WS;
    int chunk = k / CK, kl = k - chunk * CK;
    float val = 0.0f;
    if (n < HID) {
        if (kl < 16) {
            int i = chunk * 16 + kl;
            if (i < INDIM) val = wb1[i * HID + n];
        } else {
            int q = kl - 16;
            int i = chunk * 16 + (q >> 3), g = q & 7;
            if (i < INDIM) val = c1[(i * HID + n) * 8 + g];
        }
    }
    __nv_bfloat16 h = __float2bfloat16_rn(val);
    __nv_bfloat16 l = __float2bfloat16_rn(val - __bfloat162float(h));
    unsigned char* base = Wimg + (size_t)chunk * WCHUNK + kl * (WS * 2) + n * 2;
    *reinterpret_cast<__nv_bfloat16*>(base) = h;
    *reinterpret_cast<__nv_bfloat16*>(base + WCHUNK_HALF) = l;
}

// ---------------- main fused kernel ----------------
extern __shared__ __align__(16) unsigned char smem[];

__global__ __launch_bounds__(THREADS, 2)
void kan_main(const float* __restrict__ hist, const float* __restrict__ statf,
              const float* __restrict__ timef, const int* __restrict__ st_idx,
              const float* __restrict__ emb, const float* __restrict__ wb2,
              const float* __restrict__ c2, float* __restrict__ out) {
    const uint32_t sbase = smem_u32(smem);
    const int t = threadIdx.x;
    const int lane = t & 31;
    const int wid = t >> 5;
    const int wm = wid >> 2;         // m-warp: rows wm*32
    const int wn = wid & 3;          // n-warp: cols wn*16
    const int row0 = blockIdx.x * MROWS;
    int* sidx = reinterpret_cast<int*>(smem + SM_SIDX);

    if (t < MROWS) sidx[t] = st_idx[row0 + t];
    __syncthreads();

    float acc[2][2][4];
#pragma unroll
    for (int mt = 0; mt < 2; mt++)
#pragma unroll
        for (int nt = 0; nt < 2; nt++)
#pragma unroll
            for (int e = 0; e < 4; e++) acc[mt][nt][e] = 0.0f;

    const int brow = t & 63;         // build row
    const int bgrp = t >> 6;         // build input group (4 inputs)

    for (int c = 0; c < NCH; c++) {
        // ---- issue W chunk load (overlaps build) ----
        {
            const unsigned char* src = Wimg + (size_t)c * WCHUNK;
            for (int n = t; n < WCHUNK / 16; n += THREADS)
                cp16(sbase + SM_W + n * 16, src + n * 16);
            asm volatile("cp.async.commit_group;");
        }

        // ---- build A chunk: 4 cells per thread ----
        {
            int i0 = c * 16 + bgrp * 4;
            int rb = row0 + brow;
            float xv[4];
            if (i0 + 3 < 192) {
                float4 f0 = *reinterpret_cast<const float4*>(hist + (size_t)rb * 192 + i0);
                xv[0] = f0.x; xv[1] = f0.y; xv[2] = f0.z; xv[3] = f0.w;
            } else {
                int sid = sidx[brow];
#pragma unroll
                for (int j = 0; j < 4; j++) {
                    int i = i0 + j;
                    xv[j] = (i < INDIM) ? fetch_x(i, rb, hist, statf, timef, emb, sid) : 0.0f;
                }
            }
            unsigned char* ah = smem + SM_A  + brow * (AS * 2);
            unsigned char* al = smem + SM_AL + brow * (AS * 2);
            float fb[4];
#pragma unroll
            for (int j = 0; j < 4; j++) {
                float v[9];
#pragma unroll
                for (int s = 0; s < 9; s++) v[s] = 0.0f;
                if (i0 + j < INDIM) fill_slots(xv[j], v);
                fb[j] = v[0];
                uint32_t h0, l0, h1, l1, h2, l2, h3, l3;
                cvt_pair(v[1], v[2], h0, l0);
                cvt_pair(v[3], v[4], h1, l1);
                cvt_pair(v[5], v[6], h2, l2);
                cvt_pair(v[7], v[8], h3, l3);
                int off = 32 + (bgrp * 4 + j) * 16;
                *reinterpret_cast<uint4*>(ah + off) = make_uint4(h0, h1, h2, h3);
                *reinterpret_cast<uint4*>(al + off) = make_uint4(l0, l1, l2, l3);
            }
            uint32_t h0, l0, h1, l1;
            cvt_pair(fb[0], fb[1], h0, l0);
            cvt_pair(fb[2], fb[3], h1, l1);
            *reinterpret_cast<uint2*>(ah + bgrp * 8) = make_uint2(h0, h1);
            *reinterpret_cast<uint2*>(al + bgrp * 8) = make_uint2(l0, l1);
        }

        asm volatile("cp.async.wait_group 0;");
        __syncthreads();

        // ---- MMA: 9 k16 steps ----
        const uint32_t aAh = sbase + SM_A, aAl = sbase + SM_AL, aW = sbase + SM_W;
        const int arow = wm * 32 + (lane & 15);
        const int acolh = (lane >> 4) * 8;
        const int bj = lane >> 3, bw = lane & 7;
#pragma unroll
        for (int ks = 0; ks < 9; ks++) {
            uint32_t ah[2][4], al_[2][4], bh[4], bl[4];
            int kcol = ks * 16 + acolh;
#pragma unroll
            for (int mt = 0; mt < 2; mt++) {
                uint32_t ad = ((arow + mt * 16) * AS + kcol) * 2;
                ldsm4(ah[mt],  aAh + ad);
                ldsm4(al_[mt], aAl + ad);
            }
            int kk = ks * 16 + (bj & 1) * 8 + bw;
            int nn = wn * 16 + (bj >> 1) * 8;
            uint32_t bd = kk * (WS * 2) + nn * 2;
            ldsm4t(bh, aW + bd);
            ldsm4t(bl, aW + WCHUNK_HALF + bd);
#pragma unroll
            for (int mt = 0; mt < 2; mt++)
#pragma unroll
                for (int nt = 0; nt < 2; nt++) {
                    uint32_t b0h = bh[nt * 2], b1h = bh[nt * 2 + 1];
                    uint32_t b0l = bl[nt * 2], b1l = bl[nt * 2 + 1];
                    mma16816(acc[mt][nt], ah[mt],  b0h, b1h);
                    mma16816(acc[mt][nt], ah[mt],  b0l, b1l);
                    mma16816(acc[mt][nt], al_[mt], b0h, b1h);
                }
        }
        __syncthreads();
    }

    // ---- write h to smem (reuse Ah region), then layer 2 ----
    float* h = reinterpret_cast<float*>(smem + SM_A);   // h[64][66]
#pragma unroll
    for (int mt = 0; mt < 2; mt++)
#pragma unroll
        for (int nt = 0; nt < 2; nt++) {
            int r0 = wm * 32 + mt * 16 + (lane >> 2);
            int col = wn * 16 + nt * 8 + (lane & 3) * 2;
            *reinterpret_cast<float2*>(&h[r0 * 66 + col]) =
                make_float2(acc[mt][nt][0], acc[mt][nt][1]);
            *reinterpret_cast<float2*>(&h[(r0 + 8) * 66 + col]) =
                make_float2(acc[mt][nt][2], acc[mt][nt][3]);
        }
    __syncthreads();

    {
        const int row = t >> 2;
        const int sub = t & 3;
        float accum = 0.0f;
#pragma unroll
        for (int kk = 0; kk < 16; kk++) {
            int o = sub + kk * 4;
            float xv = h[row * 66 + o];
            float v = siluf(xv) * __ldg(&wb2[o]);
            int m; float n0, n1, n2, n3;
            spline_local(xv, m, n0, n1, n2, n3);
            if (m >= 0 && m <= 10) {
                int j0 = m - 3;
                if (m >= 3)           v += n0 * __ldg(&c2[o * 8 + j0]);
                if (m >= 2 && m <= 9) v += n1 * __ldg(&c2[o * 8 + j0 + 1]);
                if (m >= 1 && m <= 8) v += n2 * __ldg(&c2[o * 8 + j0 + 2]);
                if (m <= 7)           v += n3 * __ldg(&c2[o * 8 + m]);
            }
            accum += v;
        }
        accum += __shfl_xor_sync(0xffffffffu, accum, 1);
        accum += __shfl_xor_sync(0xffffffffu, accum, 2);
        if (sub == 0) out[row0 + row] = accum;
    }
}

// ---------------- launch ----------------
extern "C" void kernel_launch(void* const* d_in, const int* in_sizes, int n_in,
                              void* d_out, int out_size) {
    const float* hist  = (const float*)d_in[0];
    const float* statf = (const float*)d_in[1];
    const float* timef = (const float*)d_in[2];
    const int*   sti   = (const int*)  d_in[3];
    const float* emb   = (const float*)d_in[4];
    const float* wb1   = (const float*)d_in[5];
    const float* c1    = (const float*)d_in[6];
    const float* wb2   = (const float*)d_in[7];
    const float* c2    = (const float*)d_in[8];
    float* out = (float*)d_out;

    static int configured = 0;
    if (!configured) {
        cudaFuncSetAttribute(kan_main, cudaFuncAttributeMaxDynamicSharedMemorySize,
                             SMEM_TOTAL);
        configured = 1;
    }
    repack_kernel<<<(KTOT * WS + 255) / 256, 256>>>(wb1, c1);
    kan_main<<<BATCH / MROWS, THREADS, SMEM_TOTAL>>>(hist, statf, timef, sti, emb,
                                                     wb2, c2, out);
}